// round 2
// baseline (speedup 1.0000x reference)
#include <cuda_runtime.h>

#define NN 500000   // N_NODES upper bound
#define EE 16000000 // N_EDGES upper bound
#define TB 256
#define EPT 4       // edges per thread in edge kernels

// Scratch (no cudaMalloc allowed).
__device__ int    g_is64;       // 1 if edge_index is int64, 0 if int32
__device__ int    g_src [EE];   // decoded src indices
__device__ int    g_dst [EE];   // decoded dst indices
__device__ float  g_deg [NN];   // degree (float; exact for counts < 2^24)
__device__ float  g_dinv[NN];   // deg^{-1/2}
__device__ float  g_v   [NN];   // dinv[i] * x[i]            (gather source, layer 1)
__device__ float  g_s   [NN];   // layer-1 accumulator (init = self-loop term)
__device__ float4 g_h2d [NN];   // dinv[i] * (relu(pre1)@W2) (gather source, layer 2)

// ---------------- dtype probe ----------------
// Interpreted as int64, genuine int64 indices are always in [0, n).
// int32 data misread as int64 gives lo + hi*2^32 which is out of range
// unless hi == 0 (prob ~2e-6 per sample).
__global__ void k_probe(const void* ei, int E, int n) {
    __shared__ int ok;
    if (threadIdx.x == 0) ok = 1;
    __syncthreads();
    const long long* p = (const long long*)ei;
    long long stride = E / blockDim.x;
    if (stride < 1) stride = 1;
    long long idx = (long long)threadIdx.x * stride;
    if (idx < E) {  // first E int64 slots are in-bounds under BOTH interpretations
        long long v = p[idx];
        if (v < 0 || v >= (long long)n) ok = 0;
    }
    __syncthreads();
    if (threadIdx.x == 0) g_is64 = ok;
}

// ---------------- node kernels ----------------

__global__ void k_init_deg(int n) {
    int i = blockIdx.x * blockDim.x + threadIdx.x;
    if (i < n) g_deg[i] = 1.0f;              // self-loop
}

__global__ void k_dinv(const float* __restrict__ x, int n) {
    int i = blockIdx.x * blockDim.x + threadIdx.x;
    if (i < n) {
        float di = rsqrtf(g_deg[i]);         // deg >= 1 always (self-loop)
        g_dinv[i] = di;
        float v = di * x[i];
        g_v[i] = v;
        g_s[i] = v;                          // self-loop contribution, layer 1
    }
}

// pre1 = dinv*s ; h = relu(pre1*W1 + b1) ; h2 = h@W2 ; h2d = dinv*h2
// out init = h2d (self-loop contribution of layer 2, pre final-dinv scaling)
__global__ void k_node_mid(const float* __restrict__ W1, const float* __restrict__ b1,
                           const float* __restrict__ W2, const float* __restrict__ b2,
                           float4* __restrict__ out, int n) {
    int i = blockIdx.x * blockDim.x + threadIdx.x;
    if (i >= n) return;
    float di  = g_dinv[i];
    float pre = di * g_s[i];
    float h[4];
#pragma unroll
    for (int c = 0; c < 4; c++)
        h[c] = fmaxf(fmaf(pre, __ldg(&W1[c]), __ldg(&b1[c])), 0.0f);
    float h2[4];
#pragma unroll
    for (int c = 0; c < 4; c++) {
        float acc = h[0] * __ldg(&W2[0 * 4 + c]);
        acc = fmaf(h[1], __ldg(&W2[1 * 4 + c]), acc);
        acc = fmaf(h[2], __ldg(&W2[2 * 4 + c]), acc);
        acc = fmaf(h[3], __ldg(&W2[3 * 4 + c]), acc);
        h2[c] = di * acc;
    }
    float4 v = make_float4(h2[0], h2[1], h2[2], h2[3]);
    g_h2d[i] = v;
    out[i]   = v;                            // accumulate layer-2 messages here
}

__global__ void k_final(const float* __restrict__ b2, float4* __restrict__ out, int n) {
    int i = blockIdx.x * blockDim.x + threadIdx.x;
    if (i >= n) return;
    float di = g_dinv[i];
    float4 o = out[i];
    out[i] = make_float4(fmaf(di, o.x, __ldg(&b2[0])),
                         fmaf(di, o.y, __ldg(&b2[1])),
                         fmaf(di, o.z, __ldg(&b2[2])),
                         fmaf(di, o.w, __ldg(&b2[3])));
}

// ---------------- edge kernels ----------------

// Decode indices (either dtype) into int32 scratch + accumulate degree.
__global__ void k_convert_deg(const void* __restrict__ ei, int E, int n) {
    int is64 = g_is64;
    int e0 = blockIdx.x * blockDim.x * EPT + threadIdx.x;
#pragma unroll
    for (int k = 0; k < EPT; k++) {
        int e = e0 + k * blockDim.x;
        if (e < E) {
            int s, d;
            if (is64) {
                const long long* p = (const long long*)ei;
                s = (int)p[e];
                d = (int)p[e + E];
            } else {
                const int* p = (const int*)ei;
                s = p[e];
                d = p[e + E];
            }
            g_src[e] = s;
            g_dst[e] = d;
            if ((unsigned)d < (unsigned)n) atomicAdd(&g_deg[d], 1.0f);
        }
    }
}

__global__ void k_scatter1(int E, int n) {
    int e0 = blockIdx.x * blockDim.x * EPT + threadIdx.x;
#pragma unroll
    for (int k = 0; k < EPT; k++) {
        int e = e0 + k * blockDim.x;
        if (e < E) {
            int s = g_src[e];
            int d = g_dst[e];
            if ((unsigned)s < (unsigned)n && (unsigned)d < (unsigned)n) {
                float v = __ldg(&g_v[s]);
                atomicAdd(&g_s[d], v);
            }
        }
    }
}

__global__ void k_scatter2(float4* __restrict__ out, int E, int n) {
    int e0 = blockIdx.x * blockDim.x * EPT + threadIdx.x;
#pragma unroll
    for (int k = 0; k < EPT; k++) {
        int e = e0 + k * blockDim.x;
        if (e < E) {
            int s = g_src[e];
            int d = g_dst[e];
            if ((unsigned)s < (unsigned)n && (unsigned)d < (unsigned)n) {
                float4 m = __ldg(&g_h2d[s]);
                float* p = reinterpret_cast<float*>(&out[d]);
                asm volatile("red.global.add.v4.f32 [%0], {%1,%2,%3,%4};"
                             :: "l"(p), "f"(m.x), "f"(m.y), "f"(m.z), "f"(m.w)
                             : "memory");
            }
        }
    }
}

// ---------------- launch ----------------

extern "C" void kernel_launch(void* const* d_in, const int* in_sizes, int n_in,
                              void* d_out, int out_size) {
    const float* x  = (const float*)d_in[0];
    const void*  ei = d_in[1];                 // [2, E], int32 or int64
    const float* W1 = (const float*)d_in[2];
    const float* b1 = (const float*)d_in[3];
    const float* W2 = (const float*)d_in[4];
    const float* b2 = (const float*)d_in[5];
    float4* out = (float4*)d_out;

    int n = in_sizes[0];            // N nodes (C_in = 1)
    int E = in_sizes[1] / 2;        // element count is dtype-independent

    int nb_node = (n + TB - 1) / TB;
    int nb_edge = (E + TB * EPT - 1) / (TB * EPT);

    k_probe       <<<1, TB>>>(ei, E, n);
    k_init_deg    <<<nb_node, TB>>>(n);
    k_convert_deg <<<nb_edge, TB>>>(ei, E, n);
    k_dinv        <<<nb_node, TB>>>(x, n);
    k_scatter1    <<<nb_edge, TB>>>(E, n);
    k_node_mid    <<<nb_node, TB>>>(W1, b1, W2, b2, out, n);
    k_scatter2    <<<nb_edge, TB>>>(out, E, n);
    k_final       <<<nb_node, TB>>>(b2, out, n);
}